// round 7
// baseline (speedup 1.0000x reference)
#include <cuda_runtime.h>
#include <math.h>
#include <stdint.h>

// ---------------- problem constants ----------------
#define B_        2
#define L_        2048
#define D_        2048
#define HV_       32
#define HK_       16
#define DK_       128
#define DV_       128
#define KEY_DIM_  2048      // HK*DK
#define VAL_DIM_  4096      // HV*DV
#define CONV_DIM_ 8192      // 2*KEY_DIM + VAL_DIM
#define BL_       4096      // B*L

// ---------------- device scratch (no cudaMalloc allowed) ----------------
__device__ float g_mixed[BL_ * CONV_DIM_];   // 128 MB: qkv pre-conv; later reused for gated output
__device__ float g_cmix [BL_ * CONV_DIM_];   // 128 MB: conv+silu output
__device__ float g_z    [BL_ * VAL_DIM_];    // 64 MB
__device__ float g_core [BL_ * VAL_DIM_];    // 64 MB: scan output
__device__ float g_avec [BL_ * HV_];
__device__ float g_bvec [BL_ * HV_];
__device__ float g_eg   [BL_ * HV_];         // exp(g) per (b,l,h)
__device__ float g_beta [BL_ * HV_];
__device__ float g_rk   [BL_ * HK_];         // 1/||k||
__device__ float g_rq   [BL_ * HK_];         // 1/||q|| * DK^-0.5

// ---------------- tf32 helpers ----------------
__device__ __forceinline__ uint32_t f2tf(float x) {
    uint32_t r;
    asm("cvt.rna.tf32.f32 %0, %1;" : "=r"(r) : "f"(x));
    return r;
}

__device__ __forceinline__ void mma_tf32(float* c, const uint32_t* a, const uint32_t* b) {
    asm volatile(
        "mma.sync.aligned.m16n8k8.row.col.f32.tf32.tf32.f32 "
        "{%0,%1,%2,%3}, {%4,%5,%6,%7}, {%8,%9}, {%0,%1,%2,%3};"
        : "+f"(c[0]), "+f"(c[1]), "+f"(c[2]), "+f"(c[3])
        : "r"(a[0]), "r"(a[1]), "r"(a[2]), "r"(a[3]), "r"(b[0]), "r"(b[1]));
}

// ---------------- tf32 tensor-core GEMM: C[M,N] = A[M,K] @ B[K,N], row-major ----------------
// CTA tile 256x128, BK=16, 256 threads = 8 warps in 4x2, warp tile 64x64.
// SMEM strides conflict-free for fragment fetches:
//   As[m][k] stride 20  -> lane pattern lr*20+lc distinct mod 32
//   Bs[k][n] stride 136 -> lane pattern lc*8+lr distinct mod 32
// Double-buffered dynamic SMEM (58368 B), register prefetch of next K-slice.
// M multiple of 256, N of 128, K of 16.
#define AS_ST 20
#define BS_ST 136
#define GEMM_SMEM ((2 * 256 * AS_ST + 2 * 16 * BS_ST) * 4)

__global__ void __launch_bounds__(256, 1) mma_gemm(const float* __restrict__ A,
                                                   const float* __restrict__ Bm,
                                                   float* __restrict__ C,
                                                   int M, int N, int K) {
    extern __shared__ uint32_t sh[];
    uint32_t* AsBuf[2] = { sh, sh + 256 * AS_ST };
    uint32_t* BsBuf[2] = { sh + 2 * 256 * AS_ST, sh + 2 * 256 * AS_ST + 16 * BS_ST };

    const int tid  = threadIdx.x;
    const int warp = tid >> 5;
    const int lane = tid & 31;
    const int wy   = warp >> 1;          // 0..3  (M dir, 64 rows each)
    const int wx   = warp & 1;           // 0..1  (N dir, 64 cols each)
    const int row0 = blockIdx.y * 256;
    const int col0 = blockIdx.x * 128;

    // producer mapping
    const int ar = tid >> 2;             // 0..63 (+64,+128,+192)
    const int ac = (tid & 3) * 4;        // 0,4,8,12
    const int bk = tid >> 4;             // 0..15
    const int bc = (tid & 15) * 4;       // 0..60 (+64)

    const float* Ag = A + (size_t)(row0 + ar) * K + ac;
    const float* Bg = Bm + (size_t)bk * N + col0 + bc;
    const size_t K64 = (size_t)64 * K;

    float acc[4][8][4];
#pragma unroll
    for (int mt = 0; mt < 4; mt++)
#pragma unroll
        for (int nt = 0; nt < 8; nt++)
#pragma unroll
            for (int i = 0; i < 4; i++) acc[mt][nt][i] = 0.f;

    // prefetch first slice
    float4 av0 = *(const float4*)(Ag);
    float4 av1 = *(const float4*)(Ag + K64);
    float4 av2 = *(const float4*)(Ag + 2 * K64);
    float4 av3 = *(const float4*)(Ag + 3 * K64);
    float4 bv0 = *(const float4*)(Bg);
    float4 bv1 = *(const float4*)(Bg + 64);

    const int lr = lane >> 2;            // 0..7
    const int lc = lane & 3;             // 0..3

    int p = 0;
    for (int k0 = 0; k0 < K; k0 += 16) {
        {   // cvt + store to buffer p
            uint32_t* Ab = AsBuf[p];
            uint32_t* Bb = BsBuf[p];
            uint4 t;
            t.x = f2tf(av0.x); t.y = f2tf(av0.y); t.z = f2tf(av0.z); t.w = f2tf(av0.w);
            *(uint4*)&Ab[ar * AS_ST + ac] = t;
            t.x = f2tf(av1.x); t.y = f2tf(av1.y); t.z = f2tf(av1.z); t.w = f2tf(av1.w);
            *(uint4*)&Ab[(ar + 64) * AS_ST + ac] = t;
            t.x = f2tf(av2.x); t.y = f2tf(av2.y); t.z = f2tf(av2.z); t.w = f2tf(av2.w);
            *(uint4*)&Ab[(ar + 128) * AS_ST + ac] = t;
            t.x = f2tf(av3.x); t.y = f2tf(av3.y); t.z = f2tf(av3.z); t.w = f2tf(av3.w);
            *(uint4*)&Ab[(ar + 192) * AS_ST + ac] = t;
            t.x = f2tf(bv0.x); t.y = f2tf(bv0.y); t.z = f2tf(bv0.z); t.w = f2tf(bv0.w);
            *(uint4*)&Bb[bk * BS_ST + bc] = t;
            t.x = f2tf(bv1.x); t.y = f2tf(bv1.y); t.z = f2tf(bv1.z); t.w = f2tf(bv1.w);
            *(uint4*)&Bb[bk * BS_ST + bc + 64] = t;
        }
        __syncthreads();

        // prefetch next slice while computing this one
        if (k0 + 16 < K) {
            av0 = *(const float4*)(Ag + k0 + 16);
            av1 = *(const float4*)(Ag + K64 + k0 + 16);
            av2 = *(const float4*)(Ag + 2 * K64 + k0 + 16);
            av3 = *(const float4*)(Ag + 3 * K64 + k0 + 16);
            const float* bgk = Bg + (size_t)(k0 + 16) * N;
            bv0 = *(const float4*)(bgk);
            bv1 = *(const float4*)(bgk + 64);
        }

        const uint32_t* Abase = AsBuf[p] + (64 * wy) * AS_ST;
        const uint32_t* Bbase = BsBuf[p] + 64 * wx;

#pragma unroll
        for (int kk = 0; kk < 2; kk++) {
            const int ko = kk * 8;
            uint32_t af[4][4];
            uint32_t bf[8][2];
#pragma unroll
            for (int mt = 0; mt < 4; mt++) {
                const int r = mt * 16 + lr;
                const int c = ko + lc;
                af[mt][0] = Abase[r * AS_ST + c];
                af[mt][1] = Abase[(r + 8) * AS_ST + c];
                af[mt][2] = Abase[r * AS_ST + c + 4];
                af[mt][3] = Abase[(r + 8) * AS_ST + c + 4];
            }
#pragma unroll
            for (int nt = 0; nt < 8; nt++) {
                const int n = nt * 8 + lr;
                const int kq = ko + lc;
                bf[nt][0] = Bbase[kq * BS_ST + n];
                bf[nt][1] = Bbase[(kq + 4) * BS_ST + n];
            }
#pragma unroll
            for (int mt = 0; mt < 4; mt++)
#pragma unroll
                for (int nt = 0; nt < 8; nt++)
                    mma_tf32(acc[mt][nt], af[mt], bf[nt]);
        }
        __syncthreads();
        p ^= 1;
    }

    // epilogue
    const int lc2 = lc * 2;
#pragma unroll
    for (int mt = 0; mt < 4; mt++) {
        const int row = row0 + 64 * wy + 16 * mt + lr;
#pragma unroll
        for (int nt = 0; nt < 8; nt++) {
            const int col = col0 + 64 * wx + 8 * nt + lc2;
            *(float2*)&C[(size_t)row * N + col] =
                make_float2(acc[mt][nt][0], acc[mt][nt][1]);
            *(float2*)&C[(size_t)(row + 8) * N + col] =
                make_float2(acc[mt][nt][2], acc[mt][nt][3]);
        }
    }
}

// ---------------- skinny GEMM: b = H@W_b, a = H@W_a  (N = HV = 32) ----------------
__global__ void __launch_bounds__(256) ab_gemm(const float* __restrict__ H,
                                               const float* __restrict__ Wb,
                                               const float* __restrict__ Wa) {
    __shared__ float WbS[64][33];
    __shared__ float WaS[64][33];
    __shared__ float Hs[8][64];
    const int tid  = threadIdx.x;
    const int warp = tid >> 5;
    const int lane = tid & 31;
    const int m = blockIdx.x * 8 + warp;
    const float* hp = H + (size_t)m * D_;

    float accA = 0.f, accB = 0.f;
    for (int k0 = 0; k0 < D_; k0 += 64) {
        __syncthreads();
#pragma unroll
        for (int i = 0; i < 8; i++) {
            const int idx = tid + 256 * i;       // < 2048
            const int kk = idx >> 5, nn = idx & 31;
            WbS[kk][nn] = Wb[(size_t)(k0 + kk) * HV_ + nn];
            WaS[kk][nn] = Wa[(size_t)(k0 + kk) * HV_ + nn];
        }
        Hs[warp][lane]      = hp[k0 + lane];
        Hs[warp][lane + 32] = hp[k0 + lane + 32];
        __syncthreads();
#pragma unroll
        for (int kk = 0; kk < 64; kk++) {
            const float hv = Hs[warp][kk];
            accB += hv * WbS[kk][lane];
            accA += hv * WaS[kk][lane];
        }
    }
    g_bvec[m * HV_ + lane] = accB;
    g_avec[m * HV_ + lane] = accA;
}

// ---------------- per-(b,l,h) gates: eg = exp(g), beta = sigmoid(b) ----------------
__global__ void __launch_bounds__(256) prep_ab(const float* __restrict__ dtb,
                                               const float* __restrict__ Alog) {
    const int idx = blockIdx.x * 256 + threadIdx.x;   // < BL_*HV_
    const int h = idx & (HV_ - 1);
    float av = g_avec[idx] + dtb[h];
    float sp = (av > 20.f) ? av : log1pf(expf(av));   // softplus
    float gg = -expf(Alog[h]) * sp;
    g_eg[idx] = expf(gg);
    float bv = g_bvec[idx];
    g_beta[idx] = 1.f / (1.f + expf(-bv));
}

// ---------------- causal depthwise conv1d (K=4) + SiLU ----------------
// Chunked over L (128 steps per CTA) -> 2048 CTAs; reads g_mixed, writes g_cmix.
__global__ void __launch_bounds__(256) conv_silu(const float* __restrict__ convw) {
    const int c  = blockIdx.x * 256 + threadIdx.x;   // 0..CONV_DIM-1
    const int b  = blockIdx.y;
    const int l0 = blockIdx.z * 128;
    const float4 w = *(const float4*)(convw + c * 4);
    const float* src = g_mixed + ((size_t)b * L_ + l0) * CONV_DIM_ + c;
    float*       dst = g_cmix  + ((size_t)b * L_ + l0) * CONV_DIM_ + c;
    float x0, x1, x2;
    if (l0 == 0) {
        x0 = x1 = x2 = 0.f;
    } else {
        x0 = src[-(ptrdiff_t)3 * CONV_DIM_];
        x1 = src[-(ptrdiff_t)2 * CONV_DIM_];
        x2 = src[-(ptrdiff_t)1 * CONV_DIM_];
    }
    for (int l = 0; l < 128; l++) {
        float x3 = src[(size_t)l * CONV_DIM_];
        float y = w.x * x0 + w.y * x1 + w.z * x2 + w.w * x3;
        dst[(size_t)l * CONV_DIM_] = y / (1.f + expf(-y));
        x0 = x1; x1 = x2; x2 = x3;
    }
}

// ---------------- l2-norm scales for q,k per (b,l,hk): one warp each ----------------
__global__ void __launch_bounds__(256) prep_norm() {
    const int gw = (blockIdx.x * 256 + threadIdx.x) >> 5;   // < BL_*HK_
    const int lane = threadIdx.x & 31;
    const int bl = gw / HK_;
    const int hk = gw % HK_;
    const float* row = g_cmix + (size_t)bl * CONV_DIM_;
    const float* qp = row + hk * DK_;
    const float* kp = row + KEY_DIM_ + hk * DK_;
    float qs = 0.f, ks = 0.f;
#pragma unroll
    for (int j = 0; j < 4; j++) {
        float qv = qp[lane + 32 * j]; qs += qv * qv;
        float kv = kp[lane + 32 * j]; ks += kv * kv;
    }
#pragma unroll
    for (int o = 16; o; o >>= 1) {
        qs += __shfl_xor_sync(0xffffffffu, qs, o);
        ks += __shfl_xor_sync(0xffffffffu, ks, o);
    }
    if (lane == 0) {
        g_rq[gw] = rsqrtf(qs + 1e-6f) * 0.08838834764831845f;   // * DK^-0.5
        g_rk[gw] = rsqrtf(ks + 1e-6f);
    }
}

// ---------------- gated delta-rule scan ----------------
struct Stage { float sk[128]; float sq[128]; float sv[64]; float sc[4]; };

__global__ void __launch_bounds__(256) scan_kernel() {
    __shared__ Stage st[2];
    const int tid = threadIdx.x;
    const int vs  = blockIdx.x;      // 0..1 DV half
    const int h   = blockIdx.y;      // 0..31
    const int b   = blockIdx.z;      // 0..1
    const int hk  = h >> 1;          // repeat_interleave: h -> h / (HV/HK)
    const int col = tid >> 2;        // 0..63
    const int rb  = tid & 3;

    const float* qrow = g_cmix + (size_t)b * L_ * CONV_DIM_ + hk * DK_;
    const float* krow = qrow + KEY_DIM_;
    const float* vrow = g_cmix + (size_t)b * L_ * CONV_DIM_ + 2 * KEY_DIM_ + h * DV_ + vs * 64;
    int scidx = (b * L_) * HV_ + h;
    int nidx  = (b * L_) * HK_ + hk;
    float* orow = g_core + ((size_t)(b * L_) * HV_ + h) * DV_ + vs * 64 + col;

    float s[32];
#pragma unroll
    for (int i = 0; i < 32; i++) s[i] = 0.f;

    for (int l = 0; l < L_; l++) {
        Stage& sg = st[l & 1];
        if (tid < 128) {
            sg.sq[tid] = qrow[tid];
            sg.sk[tid] = krow[tid];
        } else if (tid < 192) {
            sg.sv[tid - 128] = vrow[tid - 128];
        } else if (tid < 196) {
            const int w = tid - 192;
            float v;
            if      (w == 0) v = g_eg[scidx];
            else if (w == 1) v = g_beta[scidx];
            else if (w == 2) v = g_rk[nidx];
            else             v = g_rq[nidx];
            sg.sc[w] = v;
        }
        __syncthreads();

        const float eg = sg.sc[0], bt = sg.sc[1], rk = sg.sc[2], rq = sg.sc[3];

        float kr[32];
        float pkv = 0.f;
#pragma unroll
        for (int i = 0; i < 32; i++) {
            const int r = rb + 4 * i;
            kr[i] = sg.sk[r];
            float sv2 = s[i] * eg;
            s[i] = sv2;
            pkv += kr[i] * sv2;
        }
        pkv += __shfl_xor_sync(0xffffffffu, pkv, 1);
        pkv += __shfl_xor_sync(0xffffffffu, pkv, 2);
        const float delta = (sg.sv[col] - pkv * rk) * bt * rk;

        float po = 0.f;
#pragma unroll
        for (int i = 0; i < 32; i++) {
            const int r = rb + 4 * i;
            float sv2 = s[i] + kr[i] * delta;
            s[i] = sv2;
            po += sg.sq[r] * sv2;
        }
        po += __shfl_xor_sync(0xffffffffu, po, 1);
        po += __shfl_xor_sync(0xffffffffu, po, 2);
        if (rb == 0) orow[0] = po * rq;

        qrow += CONV_DIM_; krow += CONV_DIM_; vrow += CONV_DIM_;
        scidx += HV_; nidx += HK_;
        orow += VAL_DIM_;
    }
}

// ---------------- gated RMSNorm ----------------
__global__ void __launch_bounds__(128) gated_norm(const float* __restrict__ normw) {
    __shared__ float red[4];
    const int tid = threadIdx.x;
    const size_t base = (size_t)blockIdx.x * 128;
    float cv = g_core[base + tid];
    float zv = g_z[base + tid];
    float gv = cv * (zv / (1.f + expf(-zv)));
    float ss = gv * gv;
#pragma unroll
    for (int o = 16; o; o >>= 1) ss += __shfl_xor_sync(0xffffffffu, ss, o);
    if ((tid & 31) == 0) red[tid >> 5] = ss;
    __syncthreads();
    float tot = red[0] + red[1] + red[2] + red[3];
    float sc = rsqrtf(tot * (1.f / 128.f) + 1e-6f);
    g_mixed[base + tid] = gv * sc * normw[tid];
}

// ---------------- launch ----------------
extern "C" void kernel_launch(void* const* d_in, const int* in_sizes, int n_in,
                              void* d_out, int out_size) {
    const float* H     = (const float*)d_in[0];
    const float* Wqkv  = (const float*)d_in[1];
    const float* Wz    = (const float*)d_in[2];
    const float* Wb    = (const float*)d_in[3];
    const float* Wa    = (const float*)d_in[4];
    const float* convw = (const float*)d_in[5];
    const float* dtb   = (const float*)d_in[6];
    const float* Alog  = (const float*)d_in[7];
    const float* normw = (const float*)d_in[8];
    const float* Wout  = (const float*)d_in[9];
    float* out = (float*)d_out;

    float* mixed = nullptr;
    float* zbuf  = nullptr;
    cudaGetSymbolAddress((void**)&mixed, g_mixed);
    cudaGetSymbolAddress((void**)&zbuf,  g_z);
    cudaFuncSetAttribute(mma_gemm, cudaFuncAttributeMaxDynamicSharedMemorySize, GEMM_SMEM);

    // 1) projections (tf32 tensor cores, 256x128 CTA tiles)
    mma_gemm<<<dim3(CONV_DIM_ / 128, BL_ / 256), 256, GEMM_SMEM>>>(H, Wqkv, mixed, BL_, CONV_DIM_, D_);
    mma_gemm<<<dim3(VAL_DIM_ / 128, BL_ / 256), 256, GEMM_SMEM>>>(H, Wz, zbuf, BL_, VAL_DIM_, D_);
    ab_gemm<<<BL_ / 8, 256>>>(H, Wb, Wa);
    prep_ab<<<(BL_ * HV_) / 256, 256>>>(dtb, Alog);

    // 2) causal conv + SiLU (g_mixed -> g_cmix), chunked over L
    conv_silu<<<dim3(CONV_DIM_ / 256, B_, L_ / 128), 256>>>(convw);

    // 3) q/k norm scales
    prep_norm<<<(BL_ * HK_) / 8, 256>>>();

    // 4) gated delta-rule recurrence
    scan_kernel<<<dim3(2, HV_, B_), 256>>>();

    // 5) gated RMSNorm (writes gated activations into g_mixed)
    gated_norm<<<BL_ * HV_, 128>>>(normw);

    // 6) output projection (tf32 tensor cores)
    mma_gemm<<<dim3(D_ / 128, BL_ / 256), 256, GEMM_SMEM>>>(mixed, Wout, out, BL_, D_, VAL_DIM_);
}

// round 9
// speedup vs baseline: 1.2364x; 1.2364x over previous
#include <cuda_runtime.h>
#include <math.h>
#include <stdint.h>

// ---------------- problem constants ----------------
#define B_        2
#define L_        2048
#define D_        2048
#define HV_       32
#define HK_       16
#define DK_       128
#define DV_       128
#define KEY_DIM_  2048      // HK*DK
#define VAL_DIM_  4096      // HV*DV
#define CONV_DIM_ 8192      // 2*KEY_DIM + VAL_DIM
#define BL_       4096      // B*L

// ---------------- device scratch (no cudaMalloc allowed) ----------------
__device__ float g_mixed[BL_ * CONV_DIM_];   // 128 MB: qkv pre-conv; later reused for gated output
__device__ float g_cmix [BL_ * CONV_DIM_];   // 128 MB: conv+silu output
__device__ float g_z    [BL_ * VAL_DIM_];    // 64 MB
__device__ float g_core [BL_ * VAL_DIM_];    // 64 MB: scan output
__device__ float g_avec [BL_ * HV_];
__device__ float g_bvec [BL_ * HV_];
__device__ float g_eg   [BL_ * HV_];         // exp(g) per (b,l,h)
__device__ float g_beta [BL_ * HV_];
__device__ float g_rk   [BL_ * HK_];         // 1/||k||
__device__ float g_rq   [BL_ * HK_];         // 1/||q|| * DK^-0.5

// ---------------- tf32 helpers ----------------
__device__ __forceinline__ uint32_t f2tf(float x) {
    uint32_t r;
    asm("cvt.rna.tf32.f32 %0, %1;" : "=r"(r) : "f"(x));
    return r;
}

__device__ __forceinline__ void mma_tf32(float* c, const uint32_t* a, const uint32_t* b) {
    asm volatile(
        "mma.sync.aligned.m16n8k8.row.col.f32.tf32.tf32.f32 "
        "{%0,%1,%2,%3}, {%4,%5,%6,%7}, {%8,%9}, {%0,%1,%2,%3};"
        : "+f"(c[0]), "+f"(c[1]), "+f"(c[2]), "+f"(c[3])
        : "r"(a[0]), "r"(a[1]), "r"(a[2]), "r"(a[3]), "r"(b[0]), "r"(b[1]));
}

// ---------------- packed f32x2 helpers (Blackwell) ----------------
typedef unsigned long long u64t;
__device__ __forceinline__ u64t pk2(float lo, float hi) {
    u64t r; asm("mov.b64 %0, {%1, %2};" : "=l"(r) : "f"(lo), "f"(hi)); return r;
}
__device__ __forceinline__ void upk2(u64t v, float& lo, float& hi) {
    asm("mov.b64 {%0, %1}, %2;" : "=f"(lo), "=f"(hi) : "l"(v));
}
__device__ __forceinline__ u64t mul2(u64t a, u64t b) {
    u64t r; asm("mul.rn.f32x2 %0, %1, %2;" : "=l"(r) : "l"(a), "l"(b)); return r;
}
__device__ __forceinline__ u64t fma2(u64t a, u64t b, u64t c) {
    u64t r; asm("fma.rn.f32x2 %0, %1, %2, %3;" : "=l"(r) : "l"(a), "l"(b), "l"(c)); return r;
}

// ---------------- tf32 tensor-core GEMM: C[M,N] = A[M,K] @ B[K,N], row-major ----------------
// (round-4 kernel: CTA 128x128, BK=16, 8 warps 2x4, warp tile 64x32 — known-good 86 TF/s)
#define AS_STRIDE 20
#define BS_STRIDE 136

__global__ void __launch_bounds__(256) mma_gemm(const float* __restrict__ A,
                                                const float* __restrict__ Bm,
                                                float* __restrict__ C,
                                                int M, int N, int K) {
    __shared__ uint32_t As[2][128 * AS_STRIDE];
    __shared__ uint32_t Bs[2][16 * BS_STRIDE];

    const int tid  = threadIdx.x;
    const int warp = tid >> 5;
    const int lane = tid & 31;
    const int wy   = warp >> 2;          // 0..1  (M dir, 64 rows)
    const int wx   = warp & 3;           // 0..3  (N dir, 32 cols)
    const int row0 = blockIdx.y * 128;
    const int col0 = blockIdx.x * 128;

    const int ar = tid >> 2;             // 0..63 (rows, +64 for second)
    const int ac = (tid & 3) * 4;        // 0,4,8,12
    const int bk = tid >> 4;             // 0..15
    const int bc = (tid & 15) * 4;       // 0..60 (+64)

    const float* Ag  = A + (size_t)(row0 + ar) * K + ac;
    const float* Ag2 = Ag + (size_t)64 * K;
    const float* Bg  = Bm + (size_t)bk * N + col0 + bc;

    float acc[4][4][4];
#pragma unroll
    for (int mt = 0; mt < 4; mt++)
#pragma unroll
        for (int nt = 0; nt < 4; nt++)
#pragma unroll
            for (int i = 0; i < 4; i++) acc[mt][nt][i] = 0.f;

    float4 a0v = *(const float4*)(Ag);
    float4 a1v = *(const float4*)(Ag2);
    float4 b0v = *(const float4*)(Bg);
    float4 b1v = *(const float4*)(Bg + 64);

    int p = 0;
    for (int k0 = 0; k0 < K; k0 += 16) {
        {
            uint32_t* Ab = As[p];
            uint32_t* Bb = Bs[p];
            uint4 t;
            t.x = f2tf(a0v.x); t.y = f2tf(a0v.y); t.z = f2tf(a0v.z); t.w = f2tf(a0v.w);
            *(uint4*)&Ab[ar * AS_STRIDE + ac] = t;
            t.x = f2tf(a1v.x); t.y = f2tf(a1v.y); t.z = f2tf(a1v.z); t.w = f2tf(a1v.w);
            *(uint4*)&Ab[(ar + 64) * AS_STRIDE + ac] = t;
            t.x = f2tf(b0v.x); t.y = f2tf(b0v.y); t.z = f2tf(b0v.z); t.w = f2tf(b0v.w);
            *(uint4*)&Bb[bk * BS_STRIDE + bc] = t;
            t.x = f2tf(b1v.x); t.y = f2tf(b1v.y); t.z = f2tf(b1v.z); t.w = f2tf(b1v.w);
            *(uint4*)&Bb[bk * BS_STRIDE + bc + 64] = t;
        }
        __syncthreads();

        if (k0 + 16 < K) {
            a0v = *(const float4*)(Ag + k0 + 16);
            a1v = *(const float4*)(Ag2 + k0 + 16);
            b0v = *(const float4*)(Bg + (size_t)(k0 + 16) * N);
            b1v = *(const float4*)(Bg + (size_t)(k0 + 16) * N + 64);
        }

        const uint32_t* Abase = As[p] + (64 * wy) * AS_STRIDE;
        const uint32_t* Bbase = Bs[p] + 32 * wx;
        const int lr = lane >> 2;        // 0..7
        const int lc = lane & 3;         // 0..3

#pragma unroll
        for (int kk = 0; kk < 2; kk++) {
            const int ko = kk * 8;
            uint32_t af[4][4];
            uint32_t bf[4][2];
#pragma unroll
            for (int mt = 0; mt < 4; mt++) {
                const int r = mt * 16 + lr;
                const int c = ko + lc;
                af[mt][0] = Abase[r * AS_STRIDE + c];
                af[mt][1] = Abase[(r + 8) * AS_STRIDE + c];
                af[mt][2] = Abase[r * AS_STRIDE + c + 4];
                af[mt][3] = Abase[(r + 8) * AS_STRIDE + c + 4];
            }
#pragma unroll
            for (int nt = 0; nt < 4; nt++) {
                const int n = nt * 8 + lr;
                const int kq = ko + lc;
                bf[nt][0] = Bbase[kq * BS_STRIDE + n];
                bf[nt][1] = Bbase[(kq + 4) * BS_STRIDE + n];
            }
#pragma unroll
            for (int mt = 0; mt < 4; mt++)
#pragma unroll
                for (int nt = 0; nt < 4; nt++)
                    mma_tf32(acc[mt][nt], af[mt], bf[nt]);
        }
        __syncthreads();
        p ^= 1;
    }

    const int lr = lane >> 2;
    const int lc2 = (lane & 3) * 2;
#pragma unroll
    for (int mt = 0; mt < 4; mt++) {
        const int row = row0 + 64 * wy + 16 * mt + lr;
#pragma unroll
        for (int nt = 0; nt < 4; nt++) {
            const int col = col0 + 32 * wx + 8 * nt + lc2;
            *(float2*)&C[(size_t)row * N + col] =
                make_float2(acc[mt][nt][0], acc[mt][nt][1]);
            *(float2*)&C[(size_t)(row + 8) * N + col] =
                make_float2(acc[mt][nt][2], acc[mt][nt][3]);
        }
    }
}

// ---------------- skinny GEMM: b = H@W_b, a = H@W_a  (N = HV = 32) ----------------
__global__ void __launch_bounds__(256) ab_gemm(const float* __restrict__ H,
                                               const float* __restrict__ Wb,
                                               const float* __restrict__ Wa) {
    __shared__ float WbS[64][33];
    __shared__ float WaS[64][33];
    __shared__ float Hs[8][64];
    const int tid  = threadIdx.x;
    const int warp = tid >> 5;
    const int lane = tid & 31;
    const int m = blockIdx.x * 8 + warp;
    const float* hp = H + (size_t)m * D_;

    float accA = 0.f, accB = 0.f;
    for (int k0 = 0; k0 < D_; k0 += 64) {
        __syncthreads();
#pragma unroll
        for (int i = 0; i < 8; i++) {
            const int idx = tid + 256 * i;       // < 2048
            const int kk = idx >> 5, nn = idx & 31;
            WbS[kk][nn] = Wb[(size_t)(k0 + kk) * HV_ + nn];
            WaS[kk][nn] = Wa[(size_t)(k0 + kk) * HV_ + nn];
        }
        Hs[warp][lane]      = hp[k0 + lane];
        Hs[warp][lane + 32] = hp[k0 + lane + 32];
        __syncthreads();
#pragma unroll
        for (int kk = 0; kk < 64; kk++) {
            const float hv = Hs[warp][kk];
            accB += hv * WbS[kk][lane];
            accA += hv * WaS[kk][lane];
        }
    }
    g_bvec[m * HV_ + lane] = accB;
    g_avec[m * HV_ + lane] = accA;
}

// ---------------- per-(b,l,h) gates: eg = exp(g), beta = sigmoid(b) ----------------
__global__ void __launch_bounds__(256) prep_ab(const float* __restrict__ dtb,
                                               const float* __restrict__ Alog) {
    const int idx = blockIdx.x * 256 + threadIdx.x;   // < BL_*HV_
    const int h = idx & (HV_ - 1);
    float av = g_avec[idx] + dtb[h];
    float sp = (av > 20.f) ? av : log1pf(expf(av));   // softplus
    float gg = -expf(Alog[h]) * sp;
    g_eg[idx] = expf(gg);
    float bv = g_bvec[idx];
    g_beta[idx] = 1.f / (1.f + expf(-bv));
}

// ---------------- causal depthwise conv1d (K=4) + SiLU ----------------
__global__ void __launch_bounds__(256) conv_silu(const float* __restrict__ convw) {
    const int c  = blockIdx.x * 256 + threadIdx.x;   // 0..CONV_DIM-1
    const int b  = blockIdx.y;
    const int l0 = blockIdx.z * 128;
    const float4 w = *(const float4*)(convw + c * 4);
    const float* src = g_mixed + ((size_t)b * L_ + l0) * CONV_DIM_ + c;
    float*       dst = g_cmix  + ((size_t)b * L_ + l0) * CONV_DIM_ + c;
    float x0, x1, x2;
    if (l0 == 0) {
        x0 = x1 = x2 = 0.f;
    } else {
        x0 = src[-(ptrdiff_t)3 * CONV_DIM_];
        x1 = src[-(ptrdiff_t)2 * CONV_DIM_];
        x2 = src[-(ptrdiff_t)1 * CONV_DIM_];
    }
    for (int l = 0; l < 128; l++) {
        float x3 = src[(size_t)l * CONV_DIM_];
        float y = w.x * x0 + w.y * x1 + w.z * x2 + w.w * x3;
        dst[(size_t)l * CONV_DIM_] = y / (1.f + expf(-y));
        x0 = x1; x1 = x2; x2 = x3;
    }
}

// ---------------- l2-norm scales for q,k per (b,l,hk): one warp each ----------------
__global__ void __launch_bounds__(256) prep_norm() {
    const int gw = (blockIdx.x * 256 + threadIdx.x) >> 5;   // < BL_*HK_
    const int lane = threadIdx.x & 31;
    const int bl = gw / HK_;
    const int hk = gw % HK_;
    const float* row = g_cmix + (size_t)bl * CONV_DIM_;
    const float* qp = row + hk * DK_;
    const float* kp = row + KEY_DIM_ + hk * DK_;
    float qs = 0.f, ks = 0.f;
#pragma unroll
    for (int j = 0; j < 4; j++) {
        float qv = qp[lane + 32 * j]; qs += qv * qv;
        float kv = kp[lane + 32 * j]; ks += kv * kv;
    }
#pragma unroll
    for (int o = 16; o; o >>= 1) {
        qs += __shfl_xor_sync(0xffffffffu, qs, o);
        ks += __shfl_xor_sync(0xffffffffu, ks, o);
    }
    if (lane == 0) {
        g_rq[gw] = rsqrtf(qs + 1e-6f) * 0.08838834764831845f;   // * DK^-0.5
        g_rk[gw] = rsqrtf(ks + 1e-6f);
    }
}

// ---------------- gated delta-rule scan (f32x2 packed) ----------------
// Grid (2 DV-halves, HV, B) = 128 CTAs, 256 threads.
// Thread (col = tid>>2, rb = tid&3) owns CONTIGUOUS rows [32*rb, 32*rb+32)
// of column (vs*64 + col): 16 packed f32x2 state regs. k/q pairs load as LDS.64
// (4 distinct addresses per warp -> conflict-free broadcast).
struct Stage { float sk[128]; float sq[128]; float sv[64]; float sc[4]; };

__global__ void __launch_bounds__(256) scan_kernel() {
    __shared__ Stage st[2];
    const int tid = threadIdx.x;
    const int vs  = blockIdx.x;      // 0..1 DV half
    const int h   = blockIdx.y;      // 0..31
    const int b   = blockIdx.z;      // 0..1
    const int hk  = h >> 1;          // repeat_interleave: h -> h / (HV/HK)
    const int col = tid >> 2;        // 0..63
    const int rb  = tid & 3;
    const int rbase = rb * 32;       // first owned row

    const float* qrow = g_cmix + (size_t)b * L_ * CONV_DIM_ + hk * DK_;
    const float* krow = qrow + KEY_DIM_;
    const float* vrow = g_cmix + (size_t)b * L_ * CONV_DIM_ + 2 * KEY_DIM_ + h * DV_ + vs * 64;
    int scidx = (b * L_) * HV_ + h;
    int nidx  = (b * L_) * HK_ + hk;
    float* orow = g_core + ((size_t)(b * L_) * HV_ + h) * DV_ + vs * 64 + col;

    u64t s2[16];
    const u64t zero2 = pk2(0.f, 0.f);
#pragma unroll
    for (int i = 0; i < 16; i++) s2[i] = zero2;

    for (int l = 0; l < L_; l++) {
        Stage& sg = st[l & 1];
        if (tid < 128) {
            sg.sq[tid] = qrow[tid];
            sg.sk[tid] = krow[tid];
        } else if (tid < 192) {
            sg.sv[tid - 128] = vrow[tid - 128];
        } else if (tid < 196) {
            const int w = tid - 192;
            float v;
            if      (w == 0) v = g_eg[scidx];
            else if (w == 1) v = g_beta[scidx];
            else if (w == 2) v = g_rk[nidx];
            else             v = g_rq[nidx];
            sg.sc[w] = v;
        }
        __syncthreads();

        const float eg = sg.sc[0], bt = sg.sc[1], rk = sg.sc[2], rq = sg.sc[3];
        const u64t eg2 = pk2(eg, eg);

        // pass 1: decay state + k·S partial (raw k; norm folded into delta)
        u64t kr2[16];
        u64t pkv2 = zero2;
#pragma unroll
        for (int i = 0; i < 16; i++) {
            const float2 kv = *(const float2*)&sg.sk[rbase + 2 * i];
            kr2[i] = pk2(kv.x, kv.y);
            const u64t sv = mul2(s2[i], eg2);
            s2[i] = sv;
            pkv2 = fma2(kr2[i], sv, pkv2);
        }
        float plo, phi;
        upk2(pkv2, plo, phi);
        float pkv = plo + phi;
        pkv += __shfl_xor_sync(0xffffffffu, pkv, 1);
        pkv += __shfl_xor_sync(0xffffffffu, pkv, 2);
        const float delta = (sg.sv[col] - pkv * rk) * bt * rk;
        const u64t d2 = pk2(delta, delta);

        // pass 2: rank-1 update + q·S partial
        u64t po2 = zero2;
#pragma unroll
        for (int i = 0; i < 16; i++) {
            const u64t sv = fma2(kr2[i], d2, s2[i]);
            s2[i] = sv;
            const float2 qv = *(const float2*)&sg.sq[rbase + 2 * i];
            po2 = fma2(pk2(qv.x, qv.y), sv, po2);
        }
        float olo, ohi;
        upk2(po2, olo, ohi);
        float po = olo + ohi;
        po += __shfl_xor_sync(0xffffffffu, po, 1);
        po += __shfl_xor_sync(0xffffffffu, po, 2);
        if (rb == 0) orow[0] = po * rq;

        qrow += CONV_DIM_; krow += CONV_DIM_; vrow += CONV_DIM_;
        scidx += HV_; nidx += HK_;
        orow += VAL_DIM_;
    }
}

// ---------------- gated RMSNorm ----------------
__global__ void __launch_bounds__(128) gated_norm(const float* __restrict__ normw) {
    __shared__ float red[4];
    const int tid = threadIdx.x;
    const size_t base = (size_t)blockIdx.x * 128;
    float cv = g_core[base + tid];
    float zv = g_z[base + tid];
    float gv = cv * (zv / (1.f + expf(-zv)));
    float ss = gv * gv;
#pragma unroll
    for (int o = 16; o; o >>= 1) ss += __shfl_xor_sync(0xffffffffu, ss, o);
    if ((tid & 31) == 0) red[tid >> 5] = ss;
    __syncthreads();
    float tot = red[0] + red[1] + red[2] + red[3];
    float sc = rsqrtf(tot * (1.f / 128.f) + 1e-6f);
    g_mixed[base + tid] = gv * sc * normw[tid];
}

// ---------------- launch ----------------
extern "C" void kernel_launch(void* const* d_in, const int* in_sizes, int n_in,
                              void* d_out, int out_size) {
    const float* H     = (const float*)d_in[0];
    const float* Wqkv  = (const float*)d_in[1];
    const float* Wz    = (const float*)d_in[2];
    const float* Wb    = (const float*)d_in[3];
    const float* Wa    = (const float*)d_in[4];
    const float* convw = (const float*)d_in[5];
    const float* dtb   = (const float*)d_in[6];
    const float* Alog  = (const float*)d_in[7];
    const float* normw = (const float*)d_in[8];
    const float* Wout  = (const float*)d_in[9];
    float* out = (float*)d_out;

    float* mixed = nullptr;
    float* zbuf  = nullptr;
    cudaGetSymbolAddress((void**)&mixed, g_mixed);
    cudaGetSymbolAddress((void**)&zbuf,  g_z);

    // 1) projections (tf32 tensor cores, 128x128 CTA tiles — round-4 proven)
    mma_gemm<<<dim3(CONV_DIM_ / 128, BL_ / 128), 256>>>(H, Wqkv, mixed, BL_, CONV_DIM_, D_);
    mma_gemm<<<dim3(VAL_DIM_ / 128, BL_ / 128), 256>>>(H, Wz, zbuf, BL_, VAL_DIM_, D_);
    ab_gemm<<<BL_ / 8, 256>>>(H, Wb, Wa);
    prep_ab<<<(BL_ * HV_) / 256, 256>>>(dtb, Alog);

    // 2) causal conv + SiLU (g_mixed -> g_cmix), chunked over L
    conv_silu<<<dim3(CONV_DIM_ / 256, B_, L_ / 128), 256>>>(convw);

    // 3) q/k norm scales
    prep_norm<<<(BL_ * HK_) / 8, 256>>>();

    // 4) gated delta-rule recurrence (f32x2 packed)
    scan_kernel<<<dim3(2, HV_, B_), 256>>>();

    // 5) gated RMSNorm (writes gated activations into g_mixed)
    gated_norm<<<BL_ * HV_, 128>>>(normw);

    // 6) output projection (tf32 tensor cores)
    mma_gemm<<<dim3(D_ / 128, BL_ / 128), 256>>>(mixed, Wout, out, BL_, D_, VAL_DIM_);
}

// round 10
// speedup vs baseline: 1.6867x; 1.3642x over previous
#include <cuda_runtime.h>
#include <math.h>
#include <stdint.h>

// ---------------- problem constants ----------------
#define B_        2
#define L_        2048
#define D_        2048
#define HV_       32
#define HK_       16
#define DK_       128
#define DV_       128
#define KEY_DIM_  2048      // HK*DK
#define VAL_DIM_  4096      // HV*DV
#define CONV_DIM_ 8192      // 2*KEY_DIM + VAL_DIM
#define BL_       4096      // B*L

// ---------------- device scratch (no cudaMalloc allowed) ----------------
__device__ float g_mixed[BL_ * CONV_DIM_];   // 128 MB: qkv pre-conv; later reused for gated output
__device__ float g_cmix [BL_ * CONV_DIM_];   // 128 MB: conv+silu output
__device__ float g_z    [BL_ * VAL_DIM_];    // 64 MB
__device__ float g_core [BL_ * VAL_DIM_];    // 64 MB: scan output
__device__ float g_avec [BL_ * HV_];
__device__ float g_bvec [BL_ * HV_];
__device__ float g_eg   [BL_ * HV_];         // exp(g) per (b,l,h)
__device__ float g_beta [BL_ * HV_];
__device__ float g_rk   [BL_ * HK_];         // 1/||k||
__device__ float g_rq   [BL_ * HK_];         // 1/||q|| * DK^-0.5

// ---------------- tf32 helpers ----------------
__device__ __forceinline__ uint32_t f2tf(float x) {
    uint32_t r;
    asm("cvt.rna.tf32.f32 %0, %1;" : "=r"(r) : "f"(x));
    return r;
}

__device__ __forceinline__ void mma_tf32(float* c, const uint32_t* a, const uint32_t* b) {
    asm volatile(
        "mma.sync.aligned.m16n8k8.row.col.f32.tf32.tf32.f32 "
        "{%0,%1,%2,%3}, {%4,%5,%6,%7}, {%8,%9}, {%0,%1,%2,%3};"
        : "+f"(c[0]), "+f"(c[1]), "+f"(c[2]), "+f"(c[3])
        : "r"(a[0]), "r"(a[1]), "r"(a[2]), "r"(a[3]), "r"(b[0]), "r"(b[1]));
}

// ---------------- packed f32x2 helpers (Blackwell) ----------------
typedef unsigned long long u64t;
__device__ __forceinline__ u64t pk2(float lo, float hi) {
    u64t r; asm("mov.b64 %0, {%1, %2};" : "=l"(r) : "f"(lo), "f"(hi)); return r;
}
__device__ __forceinline__ void upk2(u64t v, float& lo, float& hi) {
    asm("mov.b64 {%0, %1}, %2;" : "=f"(lo), "=f"(hi) : "l"(v));
}
__device__ __forceinline__ u64t mul2(u64t a, u64t b) {
    u64t r; asm("mul.rn.f32x2 %0, %1, %2;" : "=l"(r) : "l"(a), "l"(b)); return r;
}
__device__ __forceinline__ u64t fma2(u64t a, u64t b, u64t c) {
    u64t r; asm("fma.rn.f32x2 %0, %1, %2, %3;" : "=l"(r) : "l"(a), "l"(b), "l"(c)); return r;
}

// ---------------- tf32 tensor-core GEMM: C[M,N] = A[M,K] @ B[K,N], row-major ----------------
// (round-4 kernel: CTA 128x128, BK=16, 8 warps 2x4, warp tile 64x32 — known-good 86 TF/s)
#define AS_STRIDE 20
#define BS_STRIDE 136

__global__ void __launch_bounds__(256) mma_gemm(const float* __restrict__ A,
                                                const float* __restrict__ Bm,
                                                float* __restrict__ C,
                                                int M, int N, int K) {
    __shared__ uint32_t As[2][128 * AS_STRIDE];
    __shared__ uint32_t Bs[2][16 * BS_STRIDE];

    const int tid  = threadIdx.x;
    const int warp = tid >> 5;
    const int lane = tid & 31;
    const int wy   = warp >> 2;          // 0..1  (M dir, 64 rows)
    const int wx   = warp & 3;           // 0..3  (N dir, 32 cols)
    const int row0 = blockIdx.y * 128;
    const int col0 = blockIdx.x * 128;

    const int ar = tid >> 2;             // 0..63 (rows, +64 for second)
    const int ac = (tid & 3) * 4;        // 0,4,8,12
    const int bk = tid >> 4;             // 0..15
    const int bc = (tid & 15) * 4;       // 0..60 (+64)

    const float* Ag  = A + (size_t)(row0 + ar) * K + ac;
    const float* Ag2 = Ag + (size_t)64 * K;
    const float* Bg  = Bm + (size_t)bk * N + col0 + bc;

    float acc[4][4][4];
#pragma unroll
    for (int mt = 0; mt < 4; mt++)
#pragma unroll
        for (int nt = 0; nt < 4; nt++)
#pragma unroll
            for (int i = 0; i < 4; i++) acc[mt][nt][i] = 0.f;

    float4 a0v = *(const float4*)(Ag);
    float4 a1v = *(const float4*)(Ag2);
    float4 b0v = *(const float4*)(Bg);
    float4 b1v = *(const float4*)(Bg + 64);

    int p = 0;
    for (int k0 = 0; k0 < K; k0 += 16) {
        {
            uint32_t* Ab = As[p];
            uint32_t* Bb = Bs[p];
            uint4 t;
            t.x = f2tf(a0v.x); t.y = f2tf(a0v.y); t.z = f2tf(a0v.z); t.w = f2tf(a0v.w);
            *(uint4*)&Ab[ar * AS_STRIDE + ac] = t;
            t.x = f2tf(a1v.x); t.y = f2tf(a1v.y); t.z = f2tf(a1v.z); t.w = f2tf(a1v.w);
            *(uint4*)&Ab[(ar + 64) * AS_STRIDE + ac] = t;
            t.x = f2tf(b0v.x); t.y = f2tf(b0v.y); t.z = f2tf(b0v.z); t.w = f2tf(b0v.w);
            *(uint4*)&Bb[bk * BS_STRIDE + bc] = t;
            t.x = f2tf(b1v.x); t.y = f2tf(b1v.y); t.z = f2tf(b1v.z); t.w = f2tf(b1v.w);
            *(uint4*)&Bb[bk * BS_STRIDE + bc + 64] = t;
        }
        __syncthreads();

        if (k0 + 16 < K) {
            a0v = *(const float4*)(Ag + k0 + 16);
            a1v = *(const float4*)(Ag2 + k0 + 16);
            b0v = *(const float4*)(Bg + (size_t)(k0 + 16) * N);
            b1v = *(const float4*)(Bg + (size_t)(k0 + 16) * N + 64);
        }

        const uint32_t* Abase = As[p] + (64 * wy) * AS_STRIDE;
        const uint32_t* Bbase = Bs[p] + 32 * wx;
        const int lr = lane >> 2;        // 0..7
        const int lc = lane & 3;         // 0..3

#pragma unroll
        for (int kk = 0; kk < 2; kk++) {
            const int ko = kk * 8;
            uint32_t af[4][4];
            uint32_t bf[4][2];
#pragma unroll
            for (int mt = 0; mt < 4; mt++) {
                const int r = mt * 16 + lr;
                const int c = ko + lc;
                af[mt][0] = Abase[r * AS_STRIDE + c];
                af[mt][1] = Abase[(r + 8) * AS_STRIDE + c];
                af[mt][2] = Abase[r * AS_STRIDE + c + 4];
                af[mt][3] = Abase[(r + 8) * AS_STRIDE + c + 4];
            }
#pragma unroll
            for (int nt = 0; nt < 4; nt++) {
                const int n = nt * 8 + lr;
                const int kq = ko + lc;
                bf[nt][0] = Bbase[kq * BS_STRIDE + n];
                bf[nt][1] = Bbase[(kq + 4) * BS_STRIDE + n];
            }
#pragma unroll
            for (int mt = 0; mt < 4; mt++)
#pragma unroll
                for (int nt = 0; nt < 4; nt++)
                    mma_tf32(acc[mt][nt], af[mt], bf[nt]);
        }
        __syncthreads();
        p ^= 1;
    }

    const int lr = lane >> 2;
    const int lc2 = (lane & 3) * 2;
#pragma unroll
    for (int mt = 0; mt < 4; mt++) {
        const int row = row0 + 64 * wy + 16 * mt + lr;
#pragma unroll
        for (int nt = 0; nt < 4; nt++) {
            const int col = col0 + 32 * wx + 8 * nt + lc2;
            *(float2*)&C[(size_t)row * N + col] =
                make_float2(acc[mt][nt][0], acc[mt][nt][1]);
            *(float2*)&C[(size_t)(row + 8) * N + col] =
                make_float2(acc[mt][nt][2], acc[mt][nt][3]);
        }
    }
}

// ---------------- skinny GEMM: b = H@W_b, a = H@W_a  (N = HV = 32) ----------------
__global__ void __launch_bounds__(256) ab_gemm(const float* __restrict__ H,
                                               const float* __restrict__ Wb,
                                               const float* __restrict__ Wa) {
    __shared__ float WbS[64][33];
    __shared__ float WaS[64][33];
    __shared__ float Hs[8][64];
    const int tid  = threadIdx.x;
    const int warp = tid >> 5;
    const int lane = tid & 31;
    const int m = blockIdx.x * 8 + warp;
    const float* hp = H + (size_t)m * D_;

    float accA = 0.f, accB = 0.f;
    for (int k0 = 0; k0 < D_; k0 += 64) {
        __syncthreads();
#pragma unroll
        for (int i = 0; i < 8; i++) {
            const int idx = tid + 256 * i;       // < 2048
            const int kk = idx >> 5, nn = idx & 31;
            WbS[kk][nn] = Wb[(size_t)(k0 + kk) * HV_ + nn];
            WaS[kk][nn] = Wa[(size_t)(k0 + kk) * HV_ + nn];
        }
        Hs[warp][lane]      = hp[k0 + lane];
        Hs[warp][lane + 32] = hp[k0 + lane + 32];
        __syncthreads();
#pragma unroll
        for (int kk = 0; kk < 64; kk++) {
            const float hv = Hs[warp][kk];
            accB += hv * WbS[kk][lane];
            accA += hv * WaS[kk][lane];
        }
    }
    g_bvec[m * HV_ + lane] = accB;
    g_avec[m * HV_ + lane] = accA;
}

// ---------------- per-(b,l,h) gates: eg = exp(g), beta = sigmoid(b) ----------------
__global__ void __launch_bounds__(256) prep_ab(const float* __restrict__ dtb,
                                               const float* __restrict__ Alog) {
    const int idx = blockIdx.x * 256 + threadIdx.x;   // < BL_*HV_
    const int h = idx & (HV_ - 1);
    float av = g_avec[idx] + dtb[h];
    float sp = (av > 20.f) ? av : log1pf(expf(av));   // softplus
    float gg = -expf(Alog[h]) * sp;
    g_eg[idx] = expf(gg);
    float bv = g_bvec[idx];
    g_beta[idx] = 1.f / (1.f + expf(-bv));
}

// ---------------- causal depthwise conv1d (K=4) + SiLU ----------------
__global__ void __launch_bounds__(256) conv_silu(const float* __restrict__ convw) {
    const int c  = blockIdx.x * 256 + threadIdx.x;   // 0..CONV_DIM-1
    const int b  = blockIdx.y;
    const int l0 = blockIdx.z * 128;
    const float4 w = *(const float4*)(convw + c * 4);
    const float* src = g_mixed + ((size_t)b * L_ + l0) * CONV_DIM_ + c;
    float*       dst = g_cmix  + ((size_t)b * L_ + l0) * CONV_DIM_ + c;
    float x0, x1, x2;
    if (l0 == 0) {
        x0 = x1 = x2 = 0.f;
    } else {
        x0 = src[-(ptrdiff_t)3 * CONV_DIM_];
        x1 = src[-(ptrdiff_t)2 * CONV_DIM_];
        x2 = src[-(ptrdiff_t)1 * CONV_DIM_];
    }
    for (int l = 0; l < 128; l++) {
        float x3 = src[(size_t)l * CONV_DIM_];
        float y = w.x * x0 + w.y * x1 + w.z * x2 + w.w * x3;
        dst[(size_t)l * CONV_DIM_] = y / (1.f + expf(-y));
        x0 = x1; x1 = x2; x2 = x3;
    }
}

// ---------------- l2-norm scales for q,k per (b,l,hk): one warp each ----------------
__global__ void __launch_bounds__(256) prep_norm() {
    const int gw = (blockIdx.x * 256 + threadIdx.x) >> 5;   // < BL_*HK_
    const int lane = threadIdx.x & 31;
    const int bl = gw / HK_;
    const int hk = gw % HK_;
    const float* row = g_cmix + (size_t)bl * CONV_DIM_;
    const float* qp = row + hk * DK_;
    const float* kp = row + KEY_DIM_ + hk * DK_;
    float qs = 0.f, ks = 0.f;
#pragma unroll
    for (int j = 0; j < 4; j++) {
        float qv = qp[lane + 32 * j]; qs += qv * qv;
        float kv = kp[lane + 32 * j]; ks += kv * kv;
    }
#pragma unroll
    for (int o = 16; o; o >>= 1) {
        qs += __shfl_xor_sync(0xffffffffu, qs, o);
        ks += __shfl_xor_sync(0xffffffffu, ks, o);
    }
    if (lane == 0) {
        g_rq[gw] = rsqrtf(qs + 1e-6f) * 0.08838834764831845f;   // * DK^-0.5
        g_rk[gw] = rsqrtf(ks + 1e-6f);
    }
}

// ---------------- gated delta-rule scan (f32x2 packed, conflict-free pairs) ----------------
// Grid (2 DV-halves, HV, B) = 128 CTAs, 256 threads.
// Thread (col = tid>>2, rb = tid&3) owns row PAIRS {8i+2rb, 8i+2rb+1}, i=0..15,
// of column (vs*64 + col). LDS.64 addresses for fixed i are 32i+8rb bytes ->
// four disjoint bank pairs, broadcast within rb-groups: conflict-free.
struct Stage { float sk[128]; float sq[128]; float sv[64]; float sc[4]; };

__global__ void __launch_bounds__(256) scan_kernel() {
    __shared__ Stage st[2];
    const int tid = threadIdx.x;
    const int vs  = blockIdx.x;      // 0..1 DV half
    const int h   = blockIdx.y;      // 0..31
    const int b   = blockIdx.z;      // 0..1
    const int hk  = h >> 1;          // repeat_interleave: h -> h / (HV/HK)
    const int col = tid >> 2;        // 0..63
    const int rb  = tid & 3;
    const int pbase = 2 * rb;        // pair i lives at row 8*i + pbase

    const float* qrow = g_cmix + (size_t)b * L_ * CONV_DIM_ + hk * DK_;
    const float* krow = qrow + KEY_DIM_;
    const float* vrow = g_cmix + (size_t)b * L_ * CONV_DIM_ + 2 * KEY_DIM_ + h * DV_ + vs * 64;
    int scidx = (b * L_) * HV_ + h;
    int nidx  = (b * L_) * HK_ + hk;
    float* orow = g_core + ((size_t)(b * L_) * HV_ + h) * DV_ + vs * 64 + col;

    u64t s2[16];
    const u64t zero2 = pk2(0.f, 0.f);
#pragma unroll
    for (int i = 0; i < 16; i++) s2[i] = zero2;

    for (int l = 0; l < L_; l++) {
        Stage& sg = st[l & 1];
        if (tid < 128) {
            sg.sq[tid] = qrow[tid];
            sg.sk[tid] = krow[tid];
        } else if (tid < 192) {
            sg.sv[tid - 128] = vrow[tid - 128];
        } else if (tid < 196) {
            const int w = tid - 192;
            float v;
            if      (w == 0) v = g_eg[scidx];
            else if (w == 1) v = g_beta[scidx];
            else if (w == 2) v = g_rk[nidx];
            else             v = g_rq[nidx];
            sg.sc[w] = v;
        }
        __syncthreads();

        const float eg = sg.sc[0], bt = sg.sc[1], rk = sg.sc[2], rq = sg.sc[3];
        const u64t eg2 = pk2(eg, eg);

        // pass 1: decay state + k·S partial (raw k; norm folded into delta)
        u64t kr2[16];
        u64t pkv2 = zero2;
#pragma unroll
        for (int i = 0; i < 16; i++) {
            const float2 kv = *(const float2*)&sg.sk[8 * i + pbase];
            kr2[i] = pk2(kv.x, kv.y);
            const u64t sv = mul2(s2[i], eg2);
            s2[i] = sv;
            pkv2 = fma2(kr2[i], sv, pkv2);
        }
        float plo, phi;
        upk2(pkv2, plo, phi);
        float pkv = plo + phi;
        pkv += __shfl_xor_sync(0xffffffffu, pkv, 1);
        pkv += __shfl_xor_sync(0xffffffffu, pkv, 2);
        const float delta = (sg.sv[col] - pkv * rk) * bt * rk;
        const u64t d2 = pk2(delta, delta);

        // pass 2: rank-1 update + q·S partial
        u64t po2 = zero2;
#pragma unroll
        for (int i = 0; i < 16; i++) {
            const u64t sv = fma2(kr2[i], d2, s2[i]);
            s2[i] = sv;
            const float2 qv = *(const float2*)&sg.sq[8 * i + pbase];
            po2 = fma2(pk2(qv.x, qv.y), sv, po2);
        }
        float olo, ohi;
        upk2(po2, olo, ohi);
        float po = olo + ohi;
        po += __shfl_xor_sync(0xffffffffu, po, 1);
        po += __shfl_xor_sync(0xffffffffu, po, 2);
        if (rb == 0) orow[0] = po * rq;

        qrow += CONV_DIM_; krow += CONV_DIM_; vrow += CONV_DIM_;
        scidx += HV_; nidx += HK_;
        orow += VAL_DIM_;
    }
}

// ---------------- gated RMSNorm ----------------
__global__ void __launch_bounds__(128) gated_norm(const float* __restrict__ normw) {
    __shared__ float red[4];
    const int tid = threadIdx.x;
    const size_t base = (size_t)blockIdx.x * 128;
    float cv = g_core[base + tid];
    float zv = g_z[base + tid];
    float gv = cv * (zv / (1.f + expf(-zv)));
    float ss = gv * gv;
#pragma unroll
    for (int o = 16; o; o >>= 1) ss += __shfl_xor_sync(0xffffffffu, ss, o);
    if ((tid & 31) == 0) red[tid >> 5] = ss;
    __syncthreads();
    float tot = red[0] + red[1] + red[2] + red[3];
    float sc = rsqrtf(tot * (1.f / 128.f) + 1e-6f);
    g_mixed[base + tid] = gv * sc * normw[tid];
}

// ---------------- launch ----------------
extern "C" void kernel_launch(void* const* d_in, const int* in_sizes, int n_in,
                              void* d_out, int out_size) {
    const float* H     = (const float*)d_in[0];
    const float* Wqkv  = (const float*)d_in[1];
    const float* Wz    = (const float*)d_in[2];
    const float* Wb    = (const float*)d_in[3];
    const float* Wa    = (const float*)d_in[4];
    const float* convw = (const float*)d_in[5];
    const float* dtb   = (const float*)d_in[6];
    const float* Alog  = (const float*)d_in[7];
    const float* normw = (const float*)d_in[8];
    const float* Wout  = (const float*)d_in[9];
    float* out = (float*)d_out;

    float* mixed = nullptr;
    float* zbuf  = nullptr;
    cudaGetSymbolAddress((void**)&mixed, g_mixed);
    cudaGetSymbolAddress((void**)&zbuf,  g_z);

    // 1) projections (tf32 tensor cores, 128x128 CTA tiles — round-4 proven)
    mma_gemm<<<dim3(CONV_DIM_ / 128, BL_ / 128), 256>>>(H, Wqkv, mixed, BL_, CONV_DIM_, D_);
    mma_gemm<<<dim3(VAL_DIM_ / 128, BL_ / 128), 256>>>(H, Wz, zbuf, BL_, VAL_DIM_, D_);
    ab_gemm<<<BL_ / 8, 256>>>(H, Wb, Wa);
    prep_ab<<<(BL_ * HV_) / 256, 256>>>(dtb, Alog);

    // 2) causal conv + SiLU (g_mixed -> g_cmix), chunked over L
    conv_silu<<<dim3(CONV_DIM_ / 256, B_, L_ / 128), 256>>>(convw);

    // 3) q/k norm scales
    prep_norm<<<(BL_ * HK_) / 8, 256>>>();

    // 4) gated delta-rule recurrence (f32x2 packed, conflict-free)
    scan_kernel<<<dim3(2, HV_, B_), 256>>>();

    // 5) gated RMSNorm (writes gated activations into g_mixed)
    gated_norm<<<BL_ * HV_, 128>>>(normw);

    // 6) output projection (tf32 tensor cores)
    mma_gemm<<<dim3(D_ / 128, BL_ / 128), 256>>>(mixed, Wout, out, BL_, D_, VAL_DIM_);
}